// round 7
// baseline (speedup 1.0000x reference)
#include <cuda_runtime.h>
#include <cuda_fp16.h>
#include <cstdint>
#include <cmath>

// Problem constants (fixed by setup_inputs)
#define B_   8
#define NQ_  8192
#define E_   256
#define HN_  8
#define P_   4
#define DH_  32
#define NV_  16384   // 128*128

// Scratch (no cudaMalloc allowed)
__device__ __half g_v [(size_t)B_ * NV_ * E_];           // projected value, fp16
__device__ float  g_oa[(size_t)B_ * NQ_ * 96];           // [off(64) | attn(32)] per query
__device__ __half g_o [(size_t)B_ * NQ_ * E_];           // sampled output, fp16
__device__ __half g_wv16[E_ * E_];                       // W_val  fp16 [k][n]
__device__ __half g_wu16[E_ * E_];                       // W_out  fp16 [k][n]
__device__ __half g_wc16[E_ * 96];                       // [W_off|W_attn] fp16 [k][n]
__device__ float  g_bcat[96];

// ---------------------------------------------------------------------------
// PTX helpers (arch-neutral: cp.async + ldmatrix + mma.sync fp16)
// ---------------------------------------------------------------------------
#define CP_ASYNC16(saddr, gaddr) \
    asm volatile("cp.async.cg.shared.global [%0], [%1], 16;" :: "r"(saddr), "l"(gaddr) : "memory")
#define CP_COMMIT() asm volatile("cp.async.commit_group;" ::: "memory")
template<int N>
__device__ __forceinline__ void cp_wait() {
    asm volatile("cp.async.wait_group %0;" :: "n"(N) : "memory");
}

__device__ __forceinline__ uint32_t smem_u32(const void* p) {
    uint32_t a;
    asm("{ .reg .u64 t; cvta.to.shared.u64 t, %1; cvt.u32.u64 %0, t; }" : "=r"(a) : "l"(p));
    return a;
}

__device__ __forceinline__ uint32_t pack_h2(float x, float y) {
    uint32_t r;
    asm("cvt.rn.f16x2.f32 %0, %2, %1;" : "=r"(r) : "f"(x), "f"(y));
    return r;
}

#define LDMATRIX_X4(r, addr) \
    asm volatile("ldmatrix.sync.aligned.m8n8.x4.shared.b16 {%0,%1,%2,%3}, [%4];" \
        : "=r"((r)[0]), "=r"((r)[1]), "=r"((r)[2]), "=r"((r)[3]) : "r"(addr))
#define LDMATRIX_X4_T(r, addr) \
    asm volatile("ldmatrix.sync.aligned.m8n8.x4.trans.shared.b16 {%0,%1,%2,%3}, [%4];" \
        : "=r"((r)[0]), "=r"((r)[1]), "=r"((r)[2]), "=r"((r)[3]) : "r"(addr))
#define STS_V2(addr, x, y) \
    asm volatile("st.shared.v2.b32 [%0], {%1,%2};" :: "r"(addr), "r"(x), "r"(y) : "memory")

__device__ __forceinline__ void mma_f16(float d[4], const uint32_t a[4],
                                        uint32_t b0, uint32_t b1) {
    asm volatile(
        "mma.sync.aligned.m16n8k16.row.col.f32.f16.f16.f32 "
        "{%0,%1,%2,%3}, {%4,%5,%6,%7}, {%8,%9}, {%0,%1,%2,%3};"
        : "+f"(d[0]), "+f"(d[1]), "+f"(d[2]), "+f"(d[3])
        : "r"(a[0]), "r"(a[1]), "r"(a[2]), "r"(a[3]), "r"(b0), "r"(b1));
}

// ---------------------------------------------------------------------------
// Wide GEMM: C(M,256) = A(M,256) @ Wh(256,256) + bias (+R)
// 512 threads (16 warps, warp tile 32x64), BM=128, BN=256 (full N: A read once).
// 2-stage cp.async double buffer; WAR barrier between compute and refill.
// ---------------------------------------------------------------------------
template<bool AHALF, bool RESID, bool OHALF>
__global__ __launch_bounds__(512, 1)
void gemm_wide(const void* __restrict__ Av, const __half* __restrict__ Wh,
               const float* __restrict__ bias, const float* __restrict__ R,
               void* __restrict__ Cv, int M)
{
    constexpr int N = 256;
    constexpr int BM = 128, BN = 256, BK = 32, NIT = E_ / BK;  // 8
    constexpr int AP = BK + 8;        // 40 halves
    constexpr int BP = BN + 8;        // 264 halves
    constexpr int ASZ = BM * AP;      // 5120 halves
    constexpr int BSZ = BK * BP;      // 8448 halves

    extern __shared__ __half hs[];    // 2*(ASZ+BSZ) halves = 54272 B

    const int tid  = threadIdx.x;
    const int wid  = tid >> 5;        // 0..15
    const int lane = tid & 31;
    const int gid  = lane >> 2;
    const int tig  = lane & 3;

    const int row0 = blockIdx.x * BM;
    const int wr0  = (wid & 3) * 32;
    const int wc0  = (wid >> 2) * 64;

    const uint32_t sbase = smem_u32(hs);
    const uint32_t sA[2] = { sbase, sbase + (uint32_t)(ASZ + BSZ) * 2 };
    const uint32_t sB[2] = { sbase + (uint32_t)ASZ * 2, sbase + (uint32_t)(2 * ASZ + BSZ) * 2 };

    const float*  Af = (const float*)Av;
    const __half* Ah = (const __half*)Av;

    float acc[2][8][4];
#pragma unroll
    for (int mt = 0; mt < 2; mt++)
#pragma unroll
        for (int nt = 0; nt < 8; nt++)
#pragma unroll
            for (int i = 0; i < 4; i++) acc[mt][nt][i] = 0.f;

    float4 ar[2];   // fp32-A staging

    auto ldgA = [&](int k0) {
        if (!AHALF) {
#pragma unroll
            for (int i = 0; i < 2; i++) {
                int idx = tid + i * 512;
                int r = idx >> 3, c4 = idx & 7;
                ar[i] = *(const float4*)&Af[(size_t)(row0 + r) * E_ + k0 + c4 * 4];
            }
        }
    };
    auto stsA = [&](int s) {
        if (!AHALF) {
#pragma unroll
            for (int i = 0; i < 2; i++) {
                int idx = tid + i * 512;
                int r = idx >> 3, c4 = idx & 7;
                STS_V2(sA[s] + (uint32_t)(r * AP + c4 * 4) * 2,
                       pack_h2(ar[i].x, ar[i].y), pack_h2(ar[i].z, ar[i].w));
            }
        }
    };
    auto asyncA = [&](int s, int k0) {
        if (AHALF) {
            int r = tid >> 2, c8 = tid & 3;        // 512 chunks of 16B
            CP_ASYNC16(sA[s] + (uint32_t)(r * AP + c8 * 8) * 2,
                       Ah + (size_t)(row0 + r) * E_ + k0 + c8 * 8);
        }
    };
    auto asyncB = [&](int s, int k0) {
#pragma unroll
        for (int i = 0; i < 2; i++) {
            int chunk = tid + i * 512;             // 1024 chunks
            int r = chunk >> 5, c8 = chunk & 31;
            CP_ASYNC16(sB[s] + (uint32_t)(r * BP + c8 * 8) * 2,
                       Wh + (size_t)(k0 + r) * N + c8 * 8);
        }
    };

    auto compute = [&](int s) {
#pragma unroll
        for (int ks = 0; ks < 2; ks++) {
            uint32_t a0[4], a1[4];
            const uint32_t arow = (uint32_t)(lane & 15);
            const uint32_t kof  = (uint32_t)(ks * 16 + (lane >> 4) * 8);
            LDMATRIX_X4(a0, sA[s] + (uint32_t)((wr0 + arow) * AP + kof) * 2);
            LDMATRIX_X4(a1, sA[s] + (uint32_t)((wr0 + 16 + arow) * AP + kof) * 2);
#pragma unroll
            for (int ntp = 0; ntp < 4; ntp++) {
                uint32_t bb[4];
                LDMATRIX_X4_T(bb, sB[s] + (uint32_t)((ks * 16 + (lane & 15)) * BP
                                   + wc0 + ntp * 16 + (lane >> 4) * 8) * 2);
                mma_f16(acc[0][2 * ntp],     a0, bb[0], bb[1]);
                mma_f16(acc[1][2 * ntp],     a1, bb[0], bb[1]);
                mma_f16(acc[0][2 * ntp + 1], a0, bb[2], bb[3]);
                mma_f16(acc[1][2 * ntp + 1], a1, bb[2], bb[3]);
            }
        }
    };

    // ---- prologue ----
    ldgA(0); asyncA(0, 0); asyncB(0, 0); CP_COMMIT();
    stsA(0);
    ldgA(BK); asyncA(1, BK); asyncB(1, BK); CP_COMMIT();
    cp_wait<1>(); __syncthreads();

    // ---- mainloop ----
#pragma unroll
    for (int it = 0; it < NIT; it++) {
        compute(it & 1);
        if (it + 1 < NIT) {
            __syncthreads();               // WAR: protect stage (it&1) before refill
            stsA((it + 1) & 1);
            if (it + 2 < NIT) {
                ldgA((it + 2) * BK);
                asyncA(it & 1, (it + 2) * BK);
                asyncB(it & 1, (it + 2) * BK);
            }
            CP_COMMIT();
            cp_wait<1>(); __syncthreads();
        }
    }

    // ---- epilogue ----
    float*   Cf = (float*)Cv;
    __half2* Ch = (__half2*)Cv;
#pragma unroll
    for (int mt = 0; mt < 2; mt++) {
#pragma unroll
        for (int nt = 0; nt < 8; nt++) {
            const int c = wc0 + nt * 8 + 2 * tig;
            const float bx = bias[c], by = bias[c + 1];
            const int r0 = row0 + wr0 + mt * 16 + gid;
            float2 o0 = { acc[mt][nt][0] + bx, acc[mt][nt][1] + by };
            float2 o1 = { acc[mt][nt][2] + bx, acc[mt][nt][3] + by };
            if (RESID) {
                const float2 rv0 = *(const float2*)&R[(size_t)r0 * N + c];
                const float2 rv1 = *(const float2*)&R[(size_t)(r0 + 8) * N + c];
                o0.x += rv0.x; o0.y += rv0.y;
                o1.x += rv1.x; o1.y += rv1.y;
            }
            if (OHALF) {
                Ch[((size_t)r0 * N + c) >> 1]       = __floats2half2_rn(o0.x, o0.y);
                Ch[((size_t)(r0 + 8) * N + c) >> 1] = __floats2half2_rn(o1.x, o1.y);
            } else {
                *(float2*)&Cf[(size_t)r0 * N + c]       = o0;
                *(float2*)&Cf[(size_t)(r0 + 8) * N + c] = o1;
            }
        }
    }
}

// ---------------------------------------------------------------------------
// Narrow GEMM (off/attn proj): 256 threads, BM=128, BN=96 (proven config)
// ---------------------------------------------------------------------------
__global__ __launch_bounds__(256, 2)
void gemm_oa(const float* __restrict__ A, const __half* __restrict__ Wh,
             const float* __restrict__ bias, float* __restrict__ C, int M)
{
    constexpr int N = 96;
    constexpr int BM = 128, BN = 96, BK = 32, NIT = E_ / BK;
    constexpr int AP = BK + 8;
    constexpr int BP = BN + 8;
    constexpr int ASZ = BM * AP;
    constexpr int BSZ = BK * BP;
    constexpr int NTP = BN / 32;     // 3

    __shared__ __half hs[2 * (ASZ + BSZ)];

    const int tid  = threadIdx.x;
    const int wid  = tid >> 5;
    const int lane = tid & 31;
    const int gid  = lane >> 2;
    const int tig  = lane & 3;

    const int row0 = blockIdx.x * BM;
    const int wr0  = (wid & 3) * 32;
    const int wc0  = (wid >> 2) * (BN / 2);

    const uint32_t sbase = smem_u32(hs);
    const uint32_t sA[2] = { sbase, sbase + (uint32_t)(ASZ + BSZ) * 2 };
    const uint32_t sB[2] = { sbase + (uint32_t)ASZ * 2, sbase + (uint32_t)(2 * ASZ + BSZ) * 2 };

    float acc[2][BN / 16][4];
#pragma unroll
    for (int mt = 0; mt < 2; mt++)
#pragma unroll
        for (int nt = 0; nt < BN / 16; nt++)
#pragma unroll
            for (int i = 0; i < 4; i++) acc[mt][nt][i] = 0.f;

    float4 ar[4];

    auto ldgA = [&](int k0) {
#pragma unroll
        for (int i = 0; i < 4; i++) {
            int idx = tid + i * 256;
            int r = idx >> 3, c4 = idx & 7;
            ar[i] = *(const float4*)&A[(size_t)(row0 + r) * E_ + k0 + c4 * 4];
        }
    };
    auto stsA = [&](int s) {
#pragma unroll
        for (int i = 0; i < 4; i++) {
            int idx = tid + i * 256;
            int r = idx >> 3, c4 = idx & 7;
            STS_V2(sA[s] + (uint32_t)(r * AP + c4 * 4) * 2,
                   pack_h2(ar[i].x, ar[i].y), pack_h2(ar[i].z, ar[i].w));
        }
    };
    auto asyncB = [&](int s, int k0) {
        constexpr int BCH = BK * BN / 8;   // 384
#pragma unroll
        for (int i = 0; i < 2; i++) {
            int chunk = tid + i * 256;
            if (chunk < BCH) {
                int r = chunk / (BN / 8), c8 = chunk % (BN / 8);
                CP_ASYNC16(sB[s] + (uint32_t)(r * BP + c8 * 8) * 2,
                           Wh + (size_t)(k0 + r) * N + c8 * 8);
            }
        }
    };

    auto compute = [&](int s) {
#pragma unroll
        for (int ks = 0; ks < 2; ks++) {
            uint32_t a0[4], a1[4];
            const uint32_t arow = (uint32_t)(lane & 15);
            const uint32_t kof  = (uint32_t)(ks * 16 + (lane >> 4) * 8);
            LDMATRIX_X4(a0, sA[s] + (uint32_t)((wr0 + arow) * AP + kof) * 2);
            LDMATRIX_X4(a1, sA[s] + (uint32_t)((wr0 + 16 + arow) * AP + kof) * 2);
#pragma unroll
            for (int ntp = 0; ntp < NTP; ntp++) {
                uint32_t bb[4];
                LDMATRIX_X4_T(bb, sB[s] + (uint32_t)((ks * 16 + (lane & 15)) * BP
                                   + wc0 + ntp * 16 + (lane >> 4) * 8) * 2);
                mma_f16(acc[0][2 * ntp],     a0, bb[0], bb[1]);
                mma_f16(acc[1][2 * ntp],     a1, bb[0], bb[1]);
                mma_f16(acc[0][2 * ntp + 1], a0, bb[2], bb[3]);
                mma_f16(acc[1][2 * ntp + 1], a1, bb[2], bb[3]);
            }
        }
    };

    ldgA(0); asyncB(0, 0); CP_COMMIT();
    stsA(0);
    ldgA(BK); asyncB(1, BK); CP_COMMIT();
    cp_wait<1>(); __syncthreads();

#pragma unroll
    for (int it = 0; it < NIT; it++) {
        compute(it & 1);
        if (it + 1 < NIT) {
            __syncthreads();
            stsA((it + 1) & 1);
            if (it + 2 < NIT) {
                ldgA((it + 2) * BK);
                asyncB(it & 1, (it + 2) * BK);
            }
            CP_COMMIT();
            cp_wait<1>(); __syncthreads();
        }
    }

#pragma unroll
    for (int mt = 0; mt < 2; mt++) {
#pragma unroll
        for (int nt = 0; nt < BN / 16; nt++) {
            const int c = wc0 + nt * 8 + 2 * tig;
            const float bx = bias[c], by = bias[c + 1];
            const int r0 = row0 + wr0 + mt * 16 + gid;
            *(float2*)&C[(size_t)r0 * N + c] =
                make_float2(acc[mt][nt][0] + bx, acc[mt][nt][1] + by);
            *(float2*)&C[(size_t)(r0 + 8) * N + c] =
                make_float2(acc[mt][nt][2] + bx, acc[mt][nt][3] + by);
        }
    }
}

// ---------------------------------------------------------------------------
// Weight prep: fp16 conversion + off/attn concat + bias concat
// ---------------------------------------------------------------------------
__global__ void prep_weights(const float* __restrict__ Wv, const float* __restrict__ Wu,
                             const float* __restrict__ Wo, const float* __restrict__ Wa,
                             const float* __restrict__ bo, const float* __restrict__ ba)
{
    const int t = blockIdx.x * blockDim.x + threadIdx.x;
    if (t < E_ * E_) {
        g_wv16[t] = __float2half_rn(Wv[t]);
        g_wu16[t] = __float2half_rn(Wu[t]);
    }
    if (t < E_ * 96) {
        const int k = t / 96, n = t % 96;
        g_wc16[t] = __float2half_rn(n < 64 ? Wo[k * 64 + n] : Wa[k * 32 + (n - 64)]);
    }
    if (t < 96) g_bcat[t] = (t < 64) ? bo[t] : ba[t - 64];
}

// ---------------------------------------------------------------------------
// Sampling: ONE warp per (b,q). lane = 8 channels (uint4); head = lane>>2.
// ---------------------------------------------------------------------------
__global__ __launch_bounds__(256)
void sample_kernel(const float* __restrict__ ref2d, const int* __restrict__ shapes)
{
    const int gtid = blockIdx.x * blockDim.x + threadIdx.x;
    const int bq   = gtid >> 5;
    const int lane = gtid & 31;
    if (bq >= B_ * NQ_) return;
    const int b = bq >> 13;                     // NQ_ = 8192

    const int h  = lane >> 2;                   // head 0..7
    const int c0 = h * DH_ + (lane & 3) * 8;    // channel base (8 ch)

    const int Hl = shapes[0], Wl = shapes[1];
    const float fW = (float)Wl, fH = (float)Hl;

    const float rx = ref2d[(size_t)bq * 2 + 0];
    const float ry = ref2d[(size_t)bq * 2 + 1];

    const float* qa = g_oa + (size_t)bq * 96;
    const float4 lg = *(const float4*)&qa[64 + h * 4];
    const float mx = fmaxf(fmaxf(lg.x, lg.y), fmaxf(lg.z, lg.w));
    const float e0 = __expf(lg.x - mx), e1 = __expf(lg.y - mx),
                e2 = __expf(lg.z - mx), e3 = __expf(lg.w - mx);
    const float inv = 1.f / (e0 + e1 + e2 + e3);
    const float aw[P_] = { e0 * inv, e1 * inv, e2 * inv, e3 * inv };

    const float4 of0 = *(const float4*)&qa[h * 8];
    const float4 of1 = *(const float4*)&qa[h * 8 + 4];
    const float ox[P_] = { of0.x, of0.z, of1.x, of1.z };
    const float oy[P_] = { of0.y, of0.w, of1.y, of1.w };

    const __half* vb = g_v + (size_t)b * NV_ * E_ + c0;

    float acc[8] = {0.f, 0.f, 0.f, 0.f, 0.f, 0.f, 0.f, 0.f};
#pragma unroll
    for (int p = 0; p < P_; p++) {
        const float x = fmaf(rx, fW, ox[p]) - 0.5f;
        const float y = fmaf(ry, fH, oy[p]) - 0.5f;
        const float x0f = floorf(x), y0f = floorf(y);
        const int x0 = (int)x0f, y0 = (int)y0f;
        const float wx1 = x - x0f, wx0 = 1.f - wx1;
        const float wy1 = y - y0f, wy0 = 1.f - wy1;
        const float ap = aw[p];

        const int   xc[4] = { x0, x0 + 1, x0,     x0 + 1 };
        const int   yc[4] = { y0, y0,     y0 + 1, y0 + 1 };
        const float wc[4] = { wx0 * wy0, wx1 * wy0, wx0 * wy1, wx1 * wy1 };
#pragma unroll
        for (int cnr = 0; cnr < 4; cnr++) {
            const bool ok = (xc[cnr] >= 0) & (xc[cnr] < Wl) & (yc[cnr] >= 0) & (yc[cnr] < Hl);
            const int xi = min(max(xc[cnr], 0), Wl - 1);
            const int yi = min(max(yc[cnr], 0), Hl - 1);
            const float w = ok ? ap * wc[cnr] : 0.f;
            const uint4 raw = *(const uint4*)&vb[(size_t)(yi * Wl + xi) * E_];
            const float2 f0 = __half22float2(*(const __half2*)&raw.x);
            const float2 f1 = __half22float2(*(const __half2*)&raw.y);
            const float2 f2 = __half22float2(*(const __half2*)&raw.z);
            const float2 f3 = __half22float2(*(const __half2*)&raw.w);
            acc[0] = fmaf(w, f0.x, acc[0]); acc[1] = fmaf(w, f0.y, acc[1]);
            acc[2] = fmaf(w, f1.x, acc[2]); acc[3] = fmaf(w, f1.y, acc[3]);
            acc[4] = fmaf(w, f2.x, acc[4]); acc[5] = fmaf(w, f2.y, acc[5]);
            acc[6] = fmaf(w, f3.x, acc[6]); acc[7] = fmaf(w, f3.y, acc[7]);
        }
    }

    uint4 outp;
    outp.x = pack_h2(acc[0], acc[1]);
    outp.y = pack_h2(acc[2], acc[3]);
    outp.z = pack_h2(acc[4], acc[5]);
    outp.w = pack_h2(acc[6], acc[7]);
    *(uint4*)&g_o[(size_t)bq * E_ + c0] = outp;
}

// ---------------------------------------------------------------------------
extern "C" void kernel_launch(void* const* d_in, const int* in_sizes, int n_in,
                              void* d_out, int out_size)
{
    const float* query  = (const float*)d_in[0];
    const float* value  = (const float*)d_in[1];
    const float* ref2d  = (const float*)d_in[2];
    const int*   shapes = (const int*)  d_in[3];
    const float* W_off  = (const float*)d_in[4];
    const float* b_off  = (const float*)d_in[5];
    const float* W_attn = (const float*)d_in[6];
    const float* b_attn = (const float*)d_in[7];
    const float* W_val  = (const float*)d_in[8];
    const float* b_val  = (const float*)d_in[9];
    const float* W_out  = (const float*)d_in[10];
    const float* b_out  = (const float*)d_in[11];
    float* out = (float*)d_out;

    void *v_ptr, *oa_ptr, *o_ptr, *wv_ptr, *wu_ptr, *wc_ptr, *bc_ptr;
    cudaGetSymbolAddress(&v_ptr,  g_v);
    cudaGetSymbolAddress(&oa_ptr, g_oa);
    cudaGetSymbolAddress(&o_ptr,  g_o);
    cudaGetSymbolAddress(&wv_ptr, g_wv16);
    cudaGetSymbolAddress(&wu_ptr, g_wu16);
    cudaGetSymbolAddress(&wc_ptr, g_wc16);
    cudaGetSymbolAddress(&bc_ptr, g_bcat);

    // dynamic smem for the wide GEMM: 2*(5120+8448) halves = 54272 B
    const int wide_smem = 2 * (128 * 40 + 32 * 264) * 2;
    cudaFuncSetAttribute((const void*)gemm_wide<false, false, true>,
                         cudaFuncAttributeMaxDynamicSharedMemorySize, wide_smem);
    cudaFuncSetAttribute((const void*)gemm_wide<true, true, false>,
                         cudaFuncAttributeMaxDynamicSharedMemorySize, wide_smem);

    const int Mv = B_ * NV_;   // 131072
    const int Mq = B_ * NQ_;   // 65536

    // 0) weight prep (fp16 + concat)
    prep_weights<<<256, 256>>>(W_val, W_out, W_off, W_attn, b_off, b_attn);

    // 1) value projection -> fp16 g_v: (Mv,256) @ (256,256), A read once
    gemm_wide<false, false, true><<<Mv / 128, 512, wide_smem>>>(
        value, (const __half*)wv_ptr, b_val, nullptr, v_ptr, Mv);
    // 2) fused offset+attn projection: (Mq,256) @ (256,96) -> fp32 g_oa
    gemm_oa<<<Mq / 128, 256>>>(query, (const __half*)wc_ptr, (const float*)bc_ptr,
                               (float*)oa_ptr, Mq);
    // 3) softmax + bilinear sampling -> fp16 g_o (one warp per query)
    sample_kernel<<<(Mq * 32) / 256, 256>>>(ref2d, shapes);
    // 4) output projection + bias + residual -> fp32 d_out, A+R read once
    gemm_wide<true, true, false><<<Mq / 128, 512, wide_smem>>>(
        o_ptr, (const __half*)wu_ptr, b_out, query, out, Mq);
}

// round 8
// speedup vs baseline: 1.0385x; 1.0385x over previous
#include <cuda_runtime.h>
#include <cuda_fp16.h>
#include <cstdint>
#include <cmath>

// Problem constants (fixed by setup_inputs)
#define B_   8
#define NQ_  8192
#define E_   256
#define HN_  8
#define P_   4
#define DH_  32
#define NV_  16384   // 128*128

// Scratch (no cudaMalloc allowed)
__device__ __half g_v [(size_t)B_ * NV_ * E_];           // projected value, fp16
__device__ float  g_oa[(size_t)B_ * NQ_ * 96];           // [off(64) | attn(32)] per query
__device__ __half g_o [(size_t)B_ * NQ_ * E_];           // sampled output, fp16
__device__ __half g_wv16[E_ * E_];                       // W_val  fp16 [k][n]
__device__ __half g_wu16[E_ * E_];                       // W_out  fp16 [k][n]
__device__ __half g_wc16[E_ * 96];                       // [W_off|W_attn] fp16 [k][n]
__device__ float  g_bcat[96];

// ---------------------------------------------------------------------------
// PTX helpers
// ---------------------------------------------------------------------------
#define CP_ASYNC16(saddr, gaddr) \
    asm volatile("cp.async.cg.shared.global [%0], [%1], 16;" :: "r"(saddr), "l"(gaddr) : "memory")
#define CP_COMMIT() asm volatile("cp.async.commit_group;" ::: "memory")
template<int N>
__device__ __forceinline__ void cp_wait() {
    asm volatile("cp.async.wait_group %0;" :: "n"(N) : "memory");
}

__device__ __forceinline__ uint32_t smem_u32(const void* p) {
    uint32_t a;
    asm("{ .reg .u64 t; cvta.to.shared.u64 t, %1; cvt.u32.u64 %0, t; }" : "=r"(a) : "l"(p));
    return a;
}

__device__ __forceinline__ uint32_t pack_h2(float x, float y) {
    uint32_t r;
    asm("cvt.rn.f16x2.f32 %0, %2, %1;" : "=r"(r) : "f"(x), "f"(y));
    return r;
}

#define LDMATRIX_X4(r, addr) \
    asm volatile("ldmatrix.sync.aligned.m8n8.x4.shared.b16 {%0,%1,%2,%3}, [%4];" \
        : "=r"((r)[0]), "=r"((r)[1]), "=r"((r)[2]), "=r"((r)[3]) : "r"(addr))
#define LDMATRIX_X4_T(r, addr) \
    asm volatile("ldmatrix.sync.aligned.m8n8.x4.trans.shared.b16 {%0,%1,%2,%3}, [%4];" \
        : "=r"((r)[0]), "=r"((r)[1]), "=r"((r)[2]), "=r"((r)[3]) : "r"(addr))
#define STS_V2(addr, x, y) \
    asm volatile("st.shared.v2.b32 [%0], {%1,%2};" :: "r"(addr), "r"(x), "r"(y) : "memory")

__device__ __forceinline__ void mma_f16(float d[4], const uint32_t a[4],
                                        uint32_t b0, uint32_t b1) {
    asm volatile(
        "mma.sync.aligned.m16n8k16.row.col.f32.f16.f16.f32 "
        "{%0,%1,%2,%3}, {%4,%5,%6,%7}, {%8,%9}, {%0,%1,%2,%3};"
        : "+f"(d[0]), "+f"(d[1]), "+f"(d[2]), "+f"(d[3])
        : "r"(a[0]), "r"(a[1]), "r"(a[2]), "r"(a[3]), "r"(b0), "r"(b1));
}

// ---------------------------------------------------------------------------
// Wide GEMM: C(M,256) = A(M,256) @ Wh(256,256) + bias (+R)
// 512 threads, BM=128, BN=256 (A read once), 3-stage cp.async multistage:
// one __syncthreads + one cp_wait per iteration; slot (it+2)%3 refilled at
// iter it — safe because it was consumed at it-1 and the barrier covers it.
// ---------------------------------------------------------------------------
template<bool AHALF, bool RESID, bool OHALF>
__global__ __launch_bounds__(512, 1)
void gemm_wide(const void* __restrict__ Av, const __half* __restrict__ Wh,
               const float* __restrict__ bias, const float* __restrict__ R,
               void* __restrict__ Cv, int M)
{
    constexpr int N = 256;
    constexpr int BM = 128, BN = 256, BK = 32, NIT = E_ / BK;  // 8
    constexpr int ST = 3;
    constexpr int AP = BK + 8;        // 40 halves
    constexpr int BP = BN + 8;        // 264 halves
    constexpr int ASZ = BM * AP;      // 5120 halves
    constexpr int BSZ = BK * BP;      // 8448 halves

    extern __shared__ __half hs[];    // ST*(ASZ+BSZ) halves = 81408 B

    const int tid  = threadIdx.x;
    const int wid  = tid >> 5;        // 0..15
    const int lane = tid & 31;
    const int gid  = lane >> 2;
    const int tig  = lane & 3;

    const int row0 = blockIdx.x * BM;
    const int wr0  = (wid & 3) * 32;
    const int wc0  = (wid >> 2) * 64;

    const uint32_t sbase = smem_u32(hs);
    uint32_t sA[ST], sB[ST];
#pragma unroll
    for (int s = 0; s < ST; s++) {
        sA[s] = sbase + (uint32_t)(s * (ASZ + BSZ)) * 2;
        sB[s] = sA[s] + (uint32_t)ASZ * 2;
    }

    const float*  Af = (const float*)Av;
    const __half* Ah = (const __half*)Av;

    float acc[2][8][4];
#pragma unroll
    for (int mt = 0; mt < 2; mt++)
#pragma unroll
        for (int nt = 0; nt < 8; nt++)
#pragma unroll
            for (int i = 0; i < 4; i++) acc[mt][nt][i] = 0.f;

    float4 ar[2];   // fp32-A staging (tile k prefetched one iter ahead)

    auto ldgA = [&](int k0) {
        if (!AHALF) {
#pragma unroll
            for (int i = 0; i < 2; i++) {
                int idx = tid + i * 512;
                int r = idx >> 3, c4 = idx & 7;
                ar[i] = *(const float4*)&Af[(size_t)(row0 + r) * E_ + k0 + c4 * 4];
            }
        }
    };
    auto stsA = [&](int s) {
        if (!AHALF) {
#pragma unroll
            for (int i = 0; i < 2; i++) {
                int idx = tid + i * 512;
                int r = idx >> 3, c4 = idx & 7;
                STS_V2(sA[s] + (uint32_t)(r * AP + c4 * 4) * 2,
                       pack_h2(ar[i].x, ar[i].y), pack_h2(ar[i].z, ar[i].w));
            }
        }
    };
    auto asyncA = [&](int s, int k0) {
        if (AHALF) {
            int r = tid >> 2, c8 = tid & 3;
            CP_ASYNC16(sA[s] + (uint32_t)(r * AP + c8 * 8) * 2,
                       Ah + (size_t)(row0 + r) * E_ + k0 + c8 * 8);
        }
    };
    auto asyncB = [&](int s, int k0) {
#pragma unroll
        for (int i = 0; i < 2; i++) {
            int chunk = tid + i * 512;
            int r = chunk >> 5, c8 = chunk & 31;
            CP_ASYNC16(sB[s] + (uint32_t)(r * BP + c8 * 8) * 2,
                       Wh + (size_t)(k0 + r) * N + c8 * 8);
        }
    };

    auto compute = [&](int s) {
#pragma unroll
        for (int ks = 0; ks < 2; ks++) {
            uint32_t a0[4], a1[4];
            const uint32_t arow = (uint32_t)(lane & 15);
            const uint32_t kof  = (uint32_t)(ks * 16 + (lane >> 4) * 8);
            LDMATRIX_X4(a0, sA[s] + (uint32_t)((wr0 + arow) * AP + kof) * 2);
            LDMATRIX_X4(a1, sA[s] + (uint32_t)((wr0 + 16 + arow) * AP + kof) * 2);
#pragma unroll
            for (int ntp = 0; ntp < 4; ntp++) {
                uint32_t bb[4];
                LDMATRIX_X4_T(bb, sB[s] + (uint32_t)((ks * 16 + (lane & 15)) * BP
                                   + wc0 + ntp * 16 + (lane >> 4) * 8) * 2);
                mma_f16(acc[0][2 * ntp],     a0, bb[0], bb[1]);
                mma_f16(acc[1][2 * ntp],     a1, bb[0], bb[1]);
                mma_f16(acc[0][2 * ntp + 1], a0, bb[2], bb[3]);
                mma_f16(acc[1][2 * ntp + 1], a1, bb[2], bb[3]);
            }
        }
    };

    // ---- prologue: tiles 0,1 staged; A-regs prefetched for tile 2 ----
    ldgA(0);
    asyncA(0, 0); asyncB(0, 0); CP_COMMIT();
    stsA(0);
    ldgA(BK);
    asyncA(1, BK); asyncB(1, BK); CP_COMMIT();
    stsA(1);
    ldgA(2 * BK);

    // ---- mainloop: one barrier + one wait per iteration ----
#pragma unroll
    for (int it = 0; it < NIT; it++) {
        if (it == NIT - 1) cp_wait<0>(); else cp_wait<1>();
        __syncthreads();
        if (it + 2 < NIT) {
            const int s2 = (it + 2) % ST;
            stsA(s2);                                  // A tile it+2 (regs from last iter)
            asyncA(s2, (it + 2) * BK);
            asyncB(s2, (it + 2) * BK);
            CP_COMMIT();
            if (it + 3 < NIT) ldgA((it + 3) * BK);     // prefetch A regs
        }
        compute(it % ST);
    }

    // ---- epilogue ----
    float*   Cf = (float*)Cv;
    __half2* Ch = (__half2*)Cv;
#pragma unroll
    for (int mt = 0; mt < 2; mt++) {
#pragma unroll
        for (int nt = 0; nt < 8; nt++) {
            const int c = wc0 + nt * 8 + 2 * tig;
            const float bx = bias[c], by = bias[c + 1];
            const int r0 = row0 + wr0 + mt * 16 + gid;
            float2 o0 = { acc[mt][nt][0] + bx, acc[mt][nt][1] + by };
            float2 o1 = { acc[mt][nt][2] + bx, acc[mt][nt][3] + by };
            if (RESID) {
                const float2 rv0 = *(const float2*)&R[(size_t)r0 * N + c];
                const float2 rv1 = *(const float2*)&R[(size_t)(r0 + 8) * N + c];
                o0.x += rv0.x; o0.y += rv0.y;
                o1.x += rv1.x; o1.y += rv1.y;
            }
            if (OHALF) {
                Ch[((size_t)r0 * N + c) >> 1]       = __floats2half2_rn(o0.x, o0.y);
                Ch[((size_t)(r0 + 8) * N + c) >> 1] = __floats2half2_rn(o1.x, o1.y);
            } else {
                *(float2*)&Cf[(size_t)r0 * N + c]       = o0;
                *(float2*)&Cf[(size_t)(r0 + 8) * N + c] = o1;
            }
        }
    }
}

// ---------------------------------------------------------------------------
// Narrow GEMM (off/attn proj): 256 threads, BM=128, BN=96, 3-stage multistage
// ---------------------------------------------------------------------------
__global__ __launch_bounds__(256, 2)
void gemm_oa(const float* __restrict__ A, const __half* __restrict__ Wh,
             const float* __restrict__ bias, float* __restrict__ C, int M)
{
    constexpr int N = 96;
    constexpr int BM = 128, BN = 96, BK = 32, NIT = E_ / BK;
    constexpr int ST = 3;
    constexpr int AP = BK + 8;
    constexpr int BP = BN + 8;
    constexpr int ASZ = BM * AP;
    constexpr int BSZ = BK * BP;
    constexpr int NTP = BN / 32;     // 3

    __shared__ __half hs[ST * (ASZ + BSZ)];

    const int tid  = threadIdx.x;
    const int wid  = tid >> 5;
    const int lane = tid & 31;
    const int gid  = lane >> 2;
    const int tig  = lane & 3;

    const int row0 = blockIdx.x * BM;
    const int wr0  = (wid & 3) * 32;
    const int wc0  = (wid >> 2) * (BN / 2);

    const uint32_t sbase = smem_u32(hs);
    uint32_t sA[ST], sB[ST];
#pragma unroll
    for (int s = 0; s < ST; s++) {
        sA[s] = sbase + (uint32_t)(s * (ASZ + BSZ)) * 2;
        sB[s] = sA[s] + (uint32_t)ASZ * 2;
    }

    float acc[2][BN / 16][4];
#pragma unroll
    for (int mt = 0; mt < 2; mt++)
#pragma unroll
        for (int nt = 0; nt < BN / 16; nt++)
#pragma unroll
            for (int i = 0; i < 4; i++) acc[mt][nt][i] = 0.f;

    float4 ar[4];

    auto ldgA = [&](int k0) {
#pragma unroll
        for (int i = 0; i < 4; i++) {
            int idx = tid + i * 256;
            int r = idx >> 3, c4 = idx & 7;
            ar[i] = *(const float4*)&A[(size_t)(row0 + r) * E_ + k0 + c4 * 4];
        }
    };
    auto stsA = [&](int s) {
#pragma unroll
        for (int i = 0; i < 4; i++) {
            int idx = tid + i * 256;
            int r = idx >> 3, c4 = idx & 7;
            STS_V2(sA[s] + (uint32_t)(r * AP + c4 * 4) * 2,
                   pack_h2(ar[i].x, ar[i].y), pack_h2(ar[i].z, ar[i].w));
        }
    };
    auto asyncB = [&](int s, int k0) {
        constexpr int BCH = BK * BN / 8;   // 384
#pragma unroll
        for (int i = 0; i < 2; i++) {
            int chunk = tid + i * 256;
            if (chunk < BCH) {
                int r = chunk / (BN / 8), c8 = chunk % (BN / 8);
                CP_ASYNC16(sB[s] + (uint32_t)(r * BP + c8 * 8) * 2,
                           Wh + (size_t)(k0 + r) * N + c8 * 8);
            }
        }
    };

    auto compute = [&](int s) {
#pragma unroll
        for (int ks = 0; ks < 2; ks++) {
            uint32_t a0[4], a1[4];
            const uint32_t arow = (uint32_t)(lane & 15);
            const uint32_t kof  = (uint32_t)(ks * 16 + (lane >> 4) * 8);
            LDMATRIX_X4(a0, sA[s] + (uint32_t)((wr0 + arow) * AP + kof) * 2);
            LDMATRIX_X4(a1, sA[s] + (uint32_t)((wr0 + 16 + arow) * AP + kof) * 2);
#pragma unroll
            for (int ntp = 0; ntp < NTP; ntp++) {
                uint32_t bb[4];
                LDMATRIX_X4_T(bb, sB[s] + (uint32_t)((ks * 16 + (lane & 15)) * BP
                                   + wc0 + ntp * 16 + (lane >> 4) * 8) * 2);
                mma_f16(acc[0][2 * ntp],     a0, bb[0], bb[1]);
                mma_f16(acc[1][2 * ntp],     a1, bb[0], bb[1]);
                mma_f16(acc[0][2 * ntp + 1], a0, bb[2], bb[3]);
                mma_f16(acc[1][2 * ntp + 1], a1, bb[2], bb[3]);
            }
        }
    };

    ldgA(0);
    asyncB(0, 0); CP_COMMIT();
    stsA(0);
    ldgA(BK);
    asyncB(1, BK); CP_COMMIT();
    stsA(1);
    ldgA(2 * BK);

#pragma unroll
    for (int it = 0; it < NIT; it++) {
        if (it == NIT - 1) cp_wait<0>(); else cp_wait<1>();
        __syncthreads();
        if (it + 2 < NIT) {
            const int s2 = (it + 2) % ST;
            stsA(s2);
            asyncB(s2, (it + 2) * BK);
            CP_COMMIT();
            if (it + 3 < NIT) ldgA((it + 3) * BK);
        }
        compute(it % ST);
    }

#pragma unroll
    for (int mt = 0; mt < 2; mt++) {
#pragma unroll
        for (int nt = 0; nt < BN / 16; nt++) {
            const int c = wc0 + nt * 8 + 2 * tig;
            const float bx = bias[c], by = bias[c + 1];
            const int r0 = row0 + wr0 + mt * 16 + gid;
            *(float2*)&C[(size_t)r0 * N + c] =
                make_float2(acc[mt][nt][0] + bx, acc[mt][nt][1] + by);
            *(float2*)&C[(size_t)(r0 + 8) * N + c] =
                make_float2(acc[mt][nt][2] + bx, acc[mt][nt][3] + by);
        }
    }
}

// ---------------------------------------------------------------------------
// Weight prep: fp16 conversion + off/attn concat + bias concat
// ---------------------------------------------------------------------------
__global__ void prep_weights(const float* __restrict__ Wv, const float* __restrict__ Wu,
                             const float* __restrict__ Wo, const float* __restrict__ Wa,
                             const float* __restrict__ bo, const float* __restrict__ ba)
{
    const int t = blockIdx.x * blockDim.x + threadIdx.x;
    if (t < E_ * E_) {
        g_wv16[t] = __float2half_rn(Wv[t]);
        g_wu16[t] = __float2half_rn(Wu[t]);
    }
    if (t < E_ * 96) {
        const int k = t / 96, n = t % 96;
        g_wc16[t] = __float2half_rn(n < 64 ? Wo[k * 64 + n] : Wa[k * 32 + (n - 64)]);
    }
    if (t < 96) g_bcat[t] = (t < 64) ? bo[t] : ba[t - 64];
}

// ---------------------------------------------------------------------------
// Sampling: ONE warp per (b,q). lane = 8 channels (uint4); head = lane>>2.
// ---------------------------------------------------------------------------
__global__ __launch_bounds__(256)
void sample_kernel(const float* __restrict__ ref2d, const int* __restrict__ shapes)
{
    const int gtid = blockIdx.x * blockDim.x + threadIdx.x;
    const int bq   = gtid >> 5;
    const int lane = gtid & 31;
    if (bq >= B_ * NQ_) return;
    const int b = bq >> 13;                     // NQ_ = 8192

    const int h  = lane >> 2;                   // head 0..7
    const int c0 = h * DH_ + (lane & 3) * 8;    // channel base (8 ch)

    const int Hl = shapes[0], Wl = shapes[1];
    const float fW = (float)Wl, fH = (float)Hl;

    const float rx = ref2d[(size_t)bq * 2 + 0];
    const float ry = ref2d[(size_t)bq * 2 + 1];

    const float* qa = g_oa + (size_t)bq * 96;
    const float4 lg = *(const float4*)&qa[64 + h * 4];
    const float mx = fmaxf(fmaxf(lg.x, lg.y), fmaxf(lg.z, lg.w));
    const float e0 = __expf(lg.x - mx), e1 = __expf(lg.y - mx),
                e2 = __expf(lg.z - mx), e3 = __expf(lg.w - mx);
    const float inv = 1.f / (e0 + e1 + e2 + e3);
    const float aw[P_] = { e0 * inv, e1 * inv, e2 * inv, e3 * inv };

    const float4 of0 = *(const float4*)&qa[h * 8];
    const float4 of1 = *(const float4*)&qa[h * 8 + 4];
    const float ox[P_] = { of0.x, of0.z, of1.x, of1.z };
    const float oy[P_] = { of0.y, of0.w, of1.y, of1.w };

    const __half* vb = g_v + (size_t)b * NV_ * E_ + c0;

    float acc[8] = {0.f, 0.f, 0.f, 0.f, 0.f, 0.f, 0.f, 0.f};
#pragma unroll
    for (int p = 0; p < P_; p++) {
        const float x = fmaf(rx, fW, ox[p]) - 0.5f;
        const float y = fmaf(ry, fH, oy[p]) - 0.5f;
        const float x0f = floorf(x), y0f = floorf(y);
        const int x0 = (int)x0f, y0 = (int)y0f;
        const float wx1 = x - x0f, wx0 = 1.f - wx1;
        const float wy1 = y - y0f, wy0 = 1.f - wy1;
        const float ap = aw[p];

        const int   xc[4] = { x0, x0 + 1, x0,     x0 + 1 };
        const int   yc[4] = { y0, y0,     y0 + 1, y0 + 1 };
        const float wc[4] = { wx0 * wy0, wx1 * wy0, wx0 * wy1, wx1 * wy1 };
#pragma unroll
        for (int cnr = 0; cnr < 4; cnr++) {
            const bool ok = (xc[cnr] >= 0) & (xc[cnr] < Wl) & (yc[cnr] >= 0) & (yc[cnr] < Hl);
            const int xi = min(max(xc[cnr], 0), Wl - 1);
            const int yi = min(max(yc[cnr], 0), Hl - 1);
            const float w = ok ? ap * wc[cnr] : 0.f;
            const uint4 raw = *(const uint4*)&vb[(size_t)(yi * Wl + xi) * E_];
            const float2 f0 = __half22float2(*(const __half2*)&raw.x);
            const float2 f1 = __half22float2(*(const __half2*)&raw.y);
            const float2 f2 = __half22float2(*(const __half2*)&raw.z);
            const float2 f3 = __half22float2(*(const __half2*)&raw.w);
            acc[0] = fmaf(w, f0.x, acc[0]); acc[1] = fmaf(w, f0.y, acc[1]);
            acc[2] = fmaf(w, f1.x, acc[2]); acc[3] = fmaf(w, f1.y, acc[3]);
            acc[4] = fmaf(w, f2.x, acc[4]); acc[5] = fmaf(w, f2.y, acc[5]);
            acc[6] = fmaf(w, f3.x, acc[6]); acc[7] = fmaf(w, f3.y, acc[7]);
        }
    }

    uint4 outp;
    outp.x = pack_h2(acc[0], acc[1]);
    outp.y = pack_h2(acc[2], acc[3]);
    outp.z = pack_h2(acc[4], acc[5]);
    outp.w = pack_h2(acc[6], acc[7]);
    *(uint4*)&g_o[(size_t)bq * E_ + c0] = outp;
}

// ---------------------------------------------------------------------------
extern "C" void kernel_launch(void* const* d_in, const int* in_sizes, int n_in,
                              void* d_out, int out_size)
{
    const float* query  = (const float*)d_in[0];
    const float* value  = (const float*)d_in[1];
    const float* ref2d  = (const float*)d_in[2];
    const int*   shapes = (const int*)  d_in[3];
    const float* W_off  = (const float*)d_in[4];
    const float* b_off  = (const float*)d_in[5];
    const float* W_attn = (const float*)d_in[6];
    const float* b_attn = (const float*)d_in[7];
    const float* W_val  = (const float*)d_in[8];
    const float* b_val  = (const float*)d_in[9];
    const float* W_out  = (const float*)d_in[10];
    const float* b_out  = (const float*)d_in[11];
    float* out = (float*)d_out;

    void *v_ptr, *oa_ptr, *o_ptr, *wv_ptr, *wu_ptr, *wc_ptr, *bc_ptr;
    cudaGetSymbolAddress(&v_ptr,  g_v);
    cudaGetSymbolAddress(&oa_ptr, g_oa);
    cudaGetSymbolAddress(&o_ptr,  g_o);
    cudaGetSymbolAddress(&wv_ptr, g_wv16);
    cudaGetSymbolAddress(&wu_ptr, g_wu16);
    cudaGetSymbolAddress(&wc_ptr, g_wc16);
    cudaGetSymbolAddress(&bc_ptr, g_bcat);

    // dynamic smem for the wide GEMM: 3*(5120+8448) halves = 81408 B
    const int wide_smem = 3 * (128 * 40 + 32 * 264) * 2;
    cudaFuncSetAttribute((const void*)gemm_wide<false, false, true>,
                         cudaFuncAttributeMaxDynamicSharedMemorySize, wide_smem);
    cudaFuncSetAttribute((const void*)gemm_wide<true, true, false>,
                         cudaFuncAttributeMaxDynamicSharedMemorySize, wide_smem);

    const int Mv = B_ * NV_;   // 131072
    const int Mq = B_ * NQ_;   // 65536

    // 0) weight prep (fp16 + concat)
    prep_weights<<<256, 256>>>(W_val, W_out, W_off, W_attn, b_off, b_attn);

    // 1) value projection -> fp16 g_v: (Mv,256) @ (256,256), A read once
    gemm_wide<false, false, true><<<Mv / 128, 512, wide_smem>>>(
        value, (const __half*)wv_ptr, b_val, nullptr, v_ptr, Mv);
    // 2) fused offset+attn projection: (Mq,256) @ (256,96) -> fp32 g_oa
    gemm_oa<<<Mq / 128, 256>>>(query, (const __half*)wc_ptr, (const float*)bc_ptr,
                               (float*)oa_ptr, Mq);
    // 3) softmax + bilinear sampling -> fp16 g_o (one warp per query)
    sample_kernel<<<(Mq * 32) / 256, 256>>>(ref2d, shapes);
    // 4) output projection + bias + residual -> fp32 d_out, A+R read once
    gemm_wide<true, true, false><<<Mq / 128, 512, wide_smem>>>(
        o_ptr, (const __half*)wu_ptr, b_out, query, out, Mq);
}